// round 17
// baseline (speedup 1.0000x reference)
#include <cuda_runtime.h>
#include <cstdint>

// vanillaMLP fused. Round 17: round-16 (110.7us) with weight reads rebalanced:
// W2 (4 of 6 LDC.128 per j) moved from the half-rate constant port (floor 8
// cyc/SMSP -> ~94us of port time, the binding pipe) to conflict-free broadcast
// LDS.128; W1 stays in constant (128 LDC/warp, under FMA budget). FMA pipe
// becomes the ceiling again.
// Outputs: [sigma N | fea N*16 | normals N*3 | grad N*3]

#define T_SIZE  524288
#define T_MASK  (T_SIZE - 1)
#define PRIME_Y 2654435761u
#define PRIME_Z 805459861u
#define DENSITY_BIAS (-1.0f)
#define CLAMP_MAX 10.0f
#define EXP10F 22026.465794806718f

#define D0 18
#define D1 24
#define D2 32
#define D3 44
#define OFF0 0
#define OFF1 5832
#define OFF2 19656
#define OFF3 52424
#define NDENSE 137608
#define NREC (NDENSE * 4)

__device__ __align__(128) float4 g_rec[NREC + 8];

// weight staging (device) and constant destination (W1 only)
__device__   float4 gW1r4[64 * 2];    // W1 rows, first 8 cols
__device__   float4 gW2t4[64 * 4];    // W2 transposed rows
__constant__ float4 cW1r4[64 * 2];

typedef unsigned long long u64;
typedef uint32_t u32;

__device__ __forceinline__ u64 pk(float a, float b) {
    u64 r; asm("mov.b64 %0, {%1,%2};" : "=l"(r) : "f"(a), "f"(b)); return r;
}
__device__ __forceinline__ u64 pk2(float a) { return pk(a, a); }
__device__ __forceinline__ float2 upk(u64 v) {
    float2 r; asm("mov.b64 {%0,%1}, %2;" : "=f"(r.x), "=f"(r.y) : "l"(v)); return r;
}
__device__ __forceinline__ u64 fma2(u64 a, u64 b, u64 c) {
    u64 d; asm("fma.rn.f32x2 %0, %1, %2, %3;" : "=l"(d) : "l"(a), "l"(b), "l"(c)); return d;
}
__device__ __forceinline__ u64 mul2(u64 a, u64 b) {
    u64 d; asm("mul.rn.f32x2 %0, %1, %2;" : "=l"(d) : "l"(a), "l"(b)); return d;
}
__device__ __forceinline__ u64 add2(u64 a, u64 b) {
    u64 d; asm("add.rn.f32x2 %0, %1, %2;" : "=l"(d) : "l"(a), "l"(b)); return d;
}
__device__ __forceinline__ u64 neg2(u64 a) { return a ^ 0x8000000080000000ULL; }

// ---- fused setup: corner-records straight from the hash table + weights ----
__global__ void __launch_bounds__(256)
setup_kernel(const float* __restrict__ table,
             const float* __restrict__ W1,
             const float* __restrict__ W2)
{
    int idx = blockIdx.x * 256 + threadIdx.x;
    if (idx < NREC) {
        int cell = idx >> 2, q = idx & 3;
        int l, local, D;
        if (cell < OFF1)      { l = 0; local = cell;        D = D0; }
        else if (cell < OFF2) { l = 1; local = cell - OFF1; D = D1; }
        else if (cell < OFF3) { l = 2; local = cell - OFF2; D = D2; }
        else                  { l = 3; local = cell - OFF3; D = D3; }
        int z = local % D;
        int t = local / D;
        int y = t % D;
        int x = t / D;
        int ox = q >> 1, oy = q & 1;
        unsigned hb = (unsigned)(x + ox) ^ ((unsigned)(y + oy) * PRIME_Y);
        unsigned h0 = hb ^ ((unsigned)z * PRIME_Z);
        unsigned h1 = hb ^ ((unsigned)(z + 1) * PRIME_Z);
        const float2* __restrict__ tbl = (const float2*)table + (size_t)l * T_SIZE;
        float2 a = __ldg(tbl + (h0 & T_MASK));
        float2 b = __ldg(tbl + (h1 & T_MASK));
        g_rec[idx] = make_float4(a.x, a.y, b.x, b.y);
    }
    if (blockIdx.x == 0) {
        int i = threadIdx.x;
        if (i < 128) {
            int j = i >> 1, h = i & 1;
            const float* s = W1 + j * 32 + h * 4;
            gW1r4[i] = make_float4(s[0], s[1], s[2], s[3]);
        }
        int j = i >> 2, h = i & 3;
        gW2t4[i] = make_float4(W2[(4 * h + 0) * 64 + j], W2[(4 * h + 1) * 64 + j],
                               W2[(4 * h + 2) * 64 + j], W2[(4 * h + 3) * 64 + j]);
    }
}

__global__ void __launch_bounds__(128, 7)
nerf_fused_kernel(const float* __restrict__ pts,
                  float* __restrict__ out,
                  int n)
{
    __shared__ float4 sstage[128 * 5];     // warp-local gather stage (10240B)
    __shared__ u32    saccs[24 * 128];     // acc spill [component][tid] (12288B)
    __shared__ float4 sW2[64 * 4];         // W2 transposed rows (4096B)

    const int tid  = threadIdx.x;
    const int lane = tid & 31;
    const int qbase = lane & ~3;
    const int lq    = lane & 3;

    // fill W2 shared (coalesced), then one barrier
    for (int i = tid; i < 256; i += 128) sW2[i] = gW2t4[i];
    __syncthreads();

    const int pid = blockIdx.x * 128 + tid;
    const bool active = (pid < n);
    const int rp = active ? pid : (n - 1);

    float x = (__ldg(pts + (size_t)rp * 3 + 0) + 1.0f) * 0.5f;
    float y = (__ldg(pts + (size_t)rp * 3 + 1) + 1.0f) * 0.5f;
    float z = (__ldg(pts + (size_t)rp * 3 + 2) + 1.0f) * 0.5f;

    const float RES[4]  = {16.0f, 22.0f, 30.0f, 42.0f};
    const int   DIMS[4] = {D0, D1, D2, D3};
    const int   OFFS[4] = {OFF0, OFF1, OFF2, OFF3};

    u64 feat2[4];

    #pragma unroll
    for (int l = 0; l < 4; l++) {
        const float res = RES[l];
        const int   D   = DIMS[l];
        float fx = x * res, fy = y * res, fz = z * res;
        float x0 = floorf(fx), y0 = floorf(fy), z0 = floorf(fz);
        float frx = fx - x0, fry = fy - y0, frz = fz - z0;
        float mfx = 1.0f - frx, mfy = 1.0f - fry, mfz = 1.0f - frz;
        int rec = OFFS[l] + (((int)x0 * D + (int)y0) * D + (int)z0);

        // cooperative quad load into the warp-local stage slice
        #pragma unroll
        for (int i = 0; i < 4; i++) {
            int r = __shfl_sync(0xffffffffu, rec, qbase + i);
            float4 v = __ldg(g_rec + (size_t)r * 4 + lq);
            sstage[((tid & ~31) + qbase + i) * 5 + lq] = v;
        }
        __syncwarp();
        float4 v00 = sstage[tid * 5 + 0];
        float4 v01 = sstage[tid * 5 + 1];
        float4 v10 = sstage[tid * 5 + 2];
        float4 v11 = sstage[tid * 5 + 3];
        __syncwarp();   // reads complete before next level's stores

        u64 fz0 = pk2(mfz), fz1 = pk2(frz);
        u64 f01 = 0, ax = 0, ay = 0, az = 0;
        {   // (0,0)
            u64 t0 = pk(v00.x, v00.y), t1 = pk(v00.z, v00.w);
            u64 s = fma2(t0, fz0, mul2(t1, fz1));
            u64 d = add2(t1, neg2(t0));
            float wxy = mfx * mfy;
            f01 = fma2(pk2(wxy), s, f01);
            ax  = fma2(pk2(-mfy), s, ax);
            ay  = fma2(pk2(-mfx), s, ay);
            az  = fma2(pk2(wxy), d, az);
        }
        {   // (0,1)
            u64 t0 = pk(v01.x, v01.y), t1 = pk(v01.z, v01.w);
            u64 s = fma2(t0, fz0, mul2(t1, fz1));
            u64 d = add2(t1, neg2(t0));
            float wxy = mfx * fry;
            f01 = fma2(pk2(wxy), s, f01);
            ax  = fma2(pk2(-fry), s, ax);
            ay  = fma2(pk2( mfx), s, ay);
            az  = fma2(pk2(wxy), d, az);
        }
        {   // (1,0)
            u64 t0 = pk(v10.x, v10.y), t1 = pk(v10.z, v10.w);
            u64 s = fma2(t0, fz0, mul2(t1, fz1));
            u64 d = add2(t1, neg2(t0));
            float wxy = frx * mfy;
            f01 = fma2(pk2(wxy), s, f01);
            ax  = fma2(pk2( mfy), s, ax);
            ay  = fma2(pk2(-frx), s, ay);
            az  = fma2(pk2(wxy), d, az);
        }
        {   // (1,1)
            u64 t0 = pk(v11.x, v11.y), t1 = pk(v11.z, v11.w);
            u64 s = fma2(t0, fz0, mul2(t1, fz1));
            u64 d = add2(t1, neg2(t0));
            float wxy = frx * fry;
            f01 = fma2(pk2(wxy), s, f01);
            ax  = fma2(pk2( fry), s, ax);
            ay  = fma2(pk2( frx), s, ay);
            az  = fma2(pk2(wxy), d, az);
        }
        feat2[l] = f01;
        // spill encode partials (dead across the MLP) to conflict-free smem
        saccs[(l * 6 + 0) * 128 + tid] = (u32)ax;
        saccs[(l * 6 + 1) * 128 + tid] = (u32)(ax >> 32);
        saccs[(l * 6 + 2) * 128 + tid] = (u32)ay;
        saccs[(l * 6 + 3) * 128 + tid] = (u32)(ay >> 32);
        saccs[(l * 6 + 4) * 128 + tid] = (u32)az;
        saccs[(l * 6 + 5) * 128 + tid] = (u32)(az >> 32);
    }

    // ---- fused MLP forward + backward-prep (f32x2) ----
    // W1 rows from constant port (2 LDC.128/j), W2 rows from smem (4 LDS.128/j)
    u64 fea2[8];
    u64 dacc2[4];
    #pragma unroll
    for (int i = 0; i < 8; i++) fea2[i] = 0;
    #pragma unroll
    for (int l = 0; l < 4; l++) dacc2[l] = 0;

    #pragma unroll 4
    for (int j = 0; j < 64; j++) {
        float4 wa = cW1r4[j * 2 + 0];
        float4 wb = cW1r4[j * 2 + 1];
        u64 a0 = pk(wa.x, wa.y), a1 = pk(wa.z, wa.w);
        u64 a2 = pk(wb.x, wb.y), a3 = pk(wb.z, wb.w);

        u64 s = fma2(feat2[0], a0,
                fma2(feat2[1], a1,
                fma2(feat2[2], a2,
                mul2(feat2[3], a3))));
        float2 sp = upk(s);
        float hj = sp.x + sp.y;
        float hp = fmaxf(hj, 0.0f);
        u64 hp2 = pk2(hp);

        float4 c0 = sW2[j * 4 + 0];
        float4 c1 = sW2[j * 4 + 1];
        float4 c2 = sW2[j * 4 + 2];
        float4 c3 = sW2[j * 4 + 3];
        fea2[0] = fma2(hp2, pk(c0.x, c0.y), fea2[0]);
        fea2[1] = fma2(hp2, pk(c0.z, c0.w), fea2[1]);
        fea2[2] = fma2(hp2, pk(c1.x, c1.y), fea2[2]);
        fea2[3] = fma2(hp2, pk(c1.z, c1.w), fea2[3]);
        fea2[4] = fma2(hp2, pk(c2.x, c2.y), fea2[4]);
        fea2[5] = fma2(hp2, pk(c2.z, c2.w), fea2[5]);
        fea2[6] = fma2(hp2, pk(c3.x, c3.y), fea2[6]);
        fea2[7] = fma2(hp2, pk(c3.z, c3.w), fea2[7]);

        float cm = (hj > 0.0f) ? c0.x : 0.0f;   // W2[0][j] gated by relu mask
        u64 cm2 = pk2(cm);
        dacc2[0] = fma2(cm2, a0, dacc2[0]);
        dacc2[1] = fma2(cm2, a1, dacc2[1]);
        dacc2[2] = fma2(cm2, a2, dacc2[2]);
        dacc2[3] = fma2(cm2, a3, dacc2[3]);
    }

    float2 fea01 = upk(fea2[0]);
    float pre   = fea01.x + DENSITY_BIAS;
    float sigma = expf(pre);
    float g     = (pre < CLAMP_MAX) ? sigma : EXP10F;

    // ---- packed gradient fold, acc reloaded from smem ----
    u64 gx2 = 0, gy2 = 0, gz2 = 0;
    #pragma unroll
    for (int l = 0; l < 4; l++) {
        u64 dl = mul2(dacc2[l], pk2(RES[l]));
        u64 ax = ((u64)saccs[(l * 6 + 1) * 128 + tid] << 32) | saccs[(l * 6 + 0) * 128 + tid];
        u64 ay = ((u64)saccs[(l * 6 + 3) * 128 + tid] << 32) | saccs[(l * 6 + 2) * 128 + tid];
        u64 az = ((u64)saccs[(l * 6 + 5) * 128 + tid] << 32) | saccs[(l * 6 + 4) * 128 + tid];
        gx2 = fma2(dl, ax, gx2);
        gy2 = fma2(dl, ay, gy2);
        gz2 = fma2(dl, az, gz2);
    }
    float2 pxx = upk(gx2), pyy = upk(gy2), pzz = upk(gz2);
    float gx = (pxx.x + pxx.y) * g;
    float gy = (pyy.x + pyy.y) * g;
    float gz = (pzz.x + pzz.y) * g;

    float nrm = sqrtf(fmaf(gx, gx, fmaf(gy, gy, gz * gz)));
    float inv = 1.0f / nrm;

    // ---- direct outputs ----
    if (active) {
        out[pid] = sigma;
        {
            float2 f0 = upk(fea2[0]), f1 = upk(fea2[1]);
            float2 f2 = upk(fea2[2]), f3 = upk(fea2[3]);
            float2 f4 = upk(fea2[4]), f5 = upk(fea2[5]);
            float2 f6 = upk(fea2[6]), f7 = upk(fea2[7]);
            float4* feaOut = (float4*)(out + (size_t)n) + (size_t)pid * 4;
            feaOut[0] = make_float4(f0.x, f0.y, f1.x, f1.y);
            feaOut[1] = make_float4(f2.x, f2.y, f3.x, f3.y);
            feaOut[2] = make_float4(f4.x, f4.y, f5.x, f5.y);
            feaOut[3] = make_float4(f6.x, f6.y, f7.x, f7.y);
        }
        float* nOut = out + (size_t)n * 17 + (size_t)pid * 3;
        nOut[0] = gx * inv; nOut[1] = gy * inv; nOut[2] = gz * inv;
        float* gOut = out + (size_t)n * 20 + (size_t)pid * 3;
        gOut[0] = gx; gOut[1] = gy; gOut[2] = gz;
    }
}

extern "C" void kernel_launch(void* const* d_in, const int* in_sizes, int n_in,
                              void* d_out, int out_size)
{
    const float* pts   = (const float*)d_in[0];
    const float* table = (const float*)d_in[1];
    const float* W1    = (const float*)d_in[2];
    const float* W2    = (const float*)d_in[3];
    float* out = (float*)d_out;
    int n = in_sizes[0] / 3;

    setup_kernel<<<(NREC + 255) / 256, 256>>>(table, W1, W2);

    void *c1 = nullptr, *g1 = nullptr;
    cudaGetSymbolAddress(&c1, cW1r4);
    cudaGetSymbolAddress(&g1, gW1r4);
    cudaMemcpyAsync(c1, g1, 64 * 2 * sizeof(float4), cudaMemcpyDeviceToDevice, 0);

    nerf_fused_kernel<<<(n + 127) / 128, 128>>>(pts, out, n);
}